// round 5
// baseline (speedup 1.0000x reference)
#include <cuda_runtime.h>
#include <mma.h>
#include <cstdint>
#include <cstdio>

using namespace nvcuda;

#define DM   768
#define DI   1536
#define DS   64
#define DTR  48
#define SEQL 2048
#define NB   4            /* effective batch: 2 orig x 2 channel-flip */
#define MTOK (NB*SEQL)    /* 8192 token rows */
#define XPW  176          /* DTR + 2*DS */

/* ---------------- scratch (static device globals; no allocation) -------- */
__device__ float g_act1[2*DM*SEQL];   /* also reused as hdw^T */
__device__ float g_hdw [2*DM*SEQL];
__device__ float g_h2  [2*SEQL*DM];
__device__ float g_X2  [MTOK*DM];
__device__ float g_xz  [MTOK*2*DI];
__device__ float g_xmf [NB*DI*SEQL];
__device__ float g_xmb [NB*DI*SEQL];
__device__ float g_xpf [MTOK*XPW];
__device__ float g_xpb [MTOK*XPW];
__device__ float g_dttmf[MTOK*DI];    /* reused first as xm_f token-major */
__device__ float g_dttmb[MTOK*DI];    /* reused first as xm_b token-major */
__device__ float g_dtf [NB*DI*SEQL];
__device__ float g_dtb [NB*DI*SEQL];
__device__ float g_yf  [NB*DI*SEQL];
__device__ float g_yb  [NB*DI*SEQL];
__device__ float g_u   [MTOK*DI];
__device__ float g_v   [MTOK*DM];

/* ======================= small helpers ================================= */
__device__ __forceinline__ uint32_t smem_u32(const void* p) {
    uint32_t a;
    asm("{ .reg .u64 t; cvta.to.shared.u64 t, %1; cvt.u32.u64 %0, t; }" : "=r"(a) : "l"(p));
    return a;
}
__device__ __forceinline__ void cpa16(uint32_t dst, const void* src) {
    asm volatile("cp.async.cg.shared.global [%0], [%1], 16;\n" :: "r"(dst), "l"(src));
}
#define CP_COMMIT() asm volatile("cp.async.commit_group;\n" ::: "memory")
#define CP_WAIT(n)  asm volatile("cp.async.wait_group %0;\n" :: "n"(n) : "memory")

/* ================= 3xTF32 mma.sync GEMM ================================
   C[m,n] = sum_k A[m,k] * W[n,k]   with fp32-grade accuracy:
   each operand split v = hi + lo (hi = tf32-exact truncation), and
   acc += a_hi*b_lo + a_lo*b_hi + a_hi*b_hi   (lo*lo dropped, ~2^-22 rel).
   A row-major [M,K] (row stride lda), W row-major [N,K], C row-major [M,N].
   Block tile 128(M) x 128(N) x 32(K); 8 warps, each 64x32 (4x2 wmma frags).
   EPI: 0 none, 1 leaky-relu, 2 softplus(x + bias[n]).
   KPAD: K not multiple of 32 -> zero-fill the pad region.                  */
#define BKK 32
#define AST 36                       /* BKK + 4 pad, in floats */
#define STG 132                      /* staging row stride, floats */
#define SM_TOTAL (4*128*AST*4)       /* 73728 bytes */

typedef wmma::fragment<wmma::matrix_a,16,16,8,wmma::precision::tf32,wmma::row_major> AFrag;
typedef wmma::fragment<wmma::matrix_b,16,16,8,wmma::precision::tf32,wmma::col_major> BFrag;

__device__ __forceinline__ float tf32_hi(float v) {
    return __uint_as_float(__float_as_uint(v) & 0xFFFFE000u);
}

template<int EPI, bool KPAD>
__global__ __launch_bounds__(256, 2) void mma_gemm_k(
    const float* __restrict__ A, const float* __restrict__ W,
    float* __restrict__ C, const float* __restrict__ bias,
    int M, int N, int K, int lda)
{
    extern __shared__ float smf[];
    float* As[2] = { smf,             smf + 128*AST };
    float* Bs[2] = { smf + 2*128*AST, smf + 3*128*AST };
    int tid = threadIdx.x, wid = tid >> 5;
    int m0 = blockIdx.y * 128, n0 = blockIdx.x * 128;
    int wm = (wid & 1) * 64, wn = (wid >> 1) * 32;

    wmma::fragment<wmma::accumulator,16,16,8,float> acc[4][2];
    #pragma unroll
    for (int i = 0; i < 4; i++)
        #pragma unroll
        for (int j = 0; j < 2; j++) wmma::fill_fragment(acc[i][j], 0.f);

    const int NKB = (K + BKK - 1) / BKK;

    auto prefetch = [&](int kb) {
        int k0 = kb * BKK, s = kb & 1;
        #pragma unroll
        for (int i = 0; i < 4; i++) {
            int e = tid + (i << 8), r = e >> 3, q = e & 7;
            float* d = As[s] + r * AST + q * 4;
            if (!KPAD || (k0 + q * 4 < K))
                cpa16(smem_u32(d), A + (long)(m0 + r) * lda + k0 + q * 4);
            else
                *(float4*)d = make_float4(0.f, 0.f, 0.f, 0.f);
        }
        #pragma unroll
        for (int i = 0; i < 4; i++) {
            int e = tid + (i << 8), r = e >> 3, q = e & 7;
            float* d = Bs[s] + r * AST + q * 4;
            if ((n0 + r < N) && (!KPAD || (k0 + q * 4 < K)))
                cpa16(smem_u32(d), W + (long)(n0 + r) * K + k0 + q * 4);
            else
                *(float4*)d = make_float4(0.f, 0.f, 0.f, 0.f);
        }
        CP_COMMIT();
    };

    prefetch(0);
    for (int kb = 0; kb < NKB; kb++) {
        int s = kb & 1;
        if (kb + 1 < NKB) { prefetch(kb + 1); CP_WAIT(1); }
        else              { CP_WAIT(0); }
        __syncthreads();
        const float* as = As[s] + wm * AST;
        const float* bs = Bs[s] + wn * AST;
        #pragma unroll
        for (int ks = 0; ks < 4; ks++) {
            AFrag ah[4], al[4];
            #pragma unroll
            for (int i = 0; i < 4; i++) {
                wmma::load_matrix_sync(ah[i], as + i * 16 * AST + ks * 8, AST);
                #pragma unroll
                for (int t = 0; t < ah[i].num_elements; t++) {
                    float v = ah[i].x[t];
                    float h = tf32_hi(v);
                    ah[i].x[t] = h;
                    al[i].x[t] = wmma::__float_to_tf32(v - h);
                }
            }
            #pragma unroll
            for (int j = 0; j < 2; j++) {
                BFrag bh, bl;
                wmma::load_matrix_sync(bh, bs + j * 16 * AST + ks * 8, AST);
                #pragma unroll
                for (int t = 0; t < bh.num_elements; t++) {
                    float v = bh.x[t];
                    float h = tf32_hi(v);
                    bh.x[t] = h;
                    bl.x[t] = wmma::__float_to_tf32(v - h);
                }
                #pragma unroll
                for (int i = 0; i < 4; i++) {
                    wmma::mma_sync(acc[i][j], ah[i], bl, acc[i][j]);
                    wmma::mma_sync(acc[i][j], al[i], bh, acc[i][j]);
                    wmma::mma_sync(acc[i][j], ah[i], bh, acc[i][j]);
                }
            }
        }
        __syncthreads();
    }

    /* stage C through shared for coalesced, epilogued global stores */
    #pragma unroll
    for (int i = 0; i < 4; i++)
        #pragma unroll
        for (int j = 0; j < 2; j++)
            wmma::store_matrix_sync(smf + (wm + i*16) * STG + wn + j*16,
                                    acc[i][j], STG, wmma::mem_row_major);
    __syncthreads();
    #pragma unroll
    for (int it = 0; it < 16; it++) {
        int e = tid + (it << 8);
        int r = e >> 5, c4 = (e & 31) << 2;
        int n = n0 + c4;
        if (n < N) {
            float4 v = *(float4*)(smf + r * STG + c4);
            if (EPI == 1) {
                v.x = v.x > 0.f ? v.x : 0.01f * v.x;
                v.y = v.y > 0.f ? v.y : 0.01f * v.y;
                v.z = v.z > 0.f ? v.z : 0.01f * v.z;
                v.w = v.w > 0.f ? v.w : 0.01f * v.w;
            } else if (EPI == 2) {
                v.x += bias[n];     v.y += bias[n + 1];
                v.z += bias[n + 2]; v.w += bias[n + 3];
                v.x = (v.x > 20.f) ? v.x : log1pf(__expf(v.x));
                v.y = (v.y > 20.f) ? v.y : log1pf(__expf(v.y));
                v.z = (v.z > 20.f) ? v.z : log1pf(__expf(v.z));
                v.w = (v.w > 20.f) ? v.w : log1pf(__expf(v.w));
            }
            *(float4*)(C + (long)(m0 + r) * N + n) = v;
        }
    }
}

/* ---------------- 1. BatchNorm3d(eval) + LeakyReLU ---------------------- */
__global__ void bn_lrelu_k(const float* __restrict__ x, const float* __restrict__ g,
                           const float* __restrict__ be, const float* __restrict__ mu,
                           const float* __restrict__ var) {
    int i = blockIdx.x * 256 + threadIdx.x;
    if (i >= 2*DM*SEQL) return;
    int c = (i / SEQL) % DM;
    float v = (x[i] - mu[c]) * rsqrtf(var[c] + 1e-5f) * g[c] + be[c];
    g_act1[i] = v > 0.f ? v : 0.01f * v;
}

/* ---------------- 2. depthwise conv3d 3x3x3 SAME ------------------------ */
__global__ void dwconv_k(const float* __restrict__ wt) {
    int i = blockIdx.x * 256 + threadIdx.x;
    if (i >= 2*DM*SEQL) return;
    int w = i & 15, h = (i >> 4) & 15, d = (i >> 8) & 7;
    int c = (i >> 11) % DM;
    int b = i / (DM * SEQL);
    const float* wp = wt + c * 27;
    const float* ip = g_act1 + (size_t)(b*DM + c) * SEQL;
    float acc = 0.f;
    #pragma unroll
    for (int kd = 0; kd < 3; kd++) {
        int dd = d + kd - 1; if (dd < 0 || dd > 7) continue;
        #pragma unroll
        for (int kh = 0; kh < 3; kh++) {
            int hh = h + kh - 1; if (hh < 0 || hh > 15) continue;
            #pragma unroll
            for (int kw = 0; kw < 3; kw++) {
                int ww = w + kw - 1; if (ww < 0 || ww > 15) continue;
                acc += wp[kd*9 + kh*3 + kw] * ip[dd*256 + hh*16 + ww];
            }
        }
    }
    g_hdw[i] = acc;
}

/* ---------------- generic 32x32 transpose ------------------------------- */
/* in[(b*R + r)*Cc + c]  ->  out[(b*Cc + c)*R + r]                          */
__global__ void transpose_g(const float* __restrict__ in, float* __restrict__ out,
                            int R, int Cc) {
    __shared__ float s[32][33];
    int b = blockIdx.z, r0 = blockIdx.y * 32, c0 = blockIdx.x * 32;
    int tx = threadIdx.x, ty = threadIdx.y;     /* 32 x 8 */
    #pragma unroll
    for (int i = 0; i < 4; i++)
        s[ty + i*8][tx] = in[((long)(b * R + r0 + ty + i*8)) * Cc + c0 + tx];
    __syncthreads();
    #pragma unroll
    for (int i = 0; i < 4; i++)
        out[((long)(b * Cc + c0 + ty + i*8)) * R + r0 + tx] = s[tx][ty + i*8];
}

/* ---------------- 4. LayerNorm over channels; emit X2 (orig + c-flip) --- */
__global__ void ln_k(const float* __restrict__ gam, const float* __restrict__ bet) {
    int m = blockIdx.x;                 /* token 0..4095 */
    __shared__ float red[16];
    const float* row = g_h2 + (size_t)m * DM;
    float s = 0.f, s2 = 0.f;
    for (int c = threadIdx.x; c < DM; c += 256) { float v = row[c]; s += v; s2 += v*v; }
    #pragma unroll
    for (int o = 16; o; o >>= 1) {
        s  += __shfl_xor_sync(~0u, s, o);
        s2 += __shfl_xor_sync(~0u, s2, o);
    }
    int wid = threadIdx.x >> 5, ln = threadIdx.x & 31;
    if (ln == 0) { red[wid] = s; red[8 + wid] = s2; }
    __syncthreads();
    float ts = 0.f, ts2 = 0.f;
    #pragma unroll
    for (int i = 0; i < 8; i++) { ts += red[i]; ts2 += red[8 + i]; }
    float mu = ts / 768.f;
    float var = ts2 / 768.f - mu * mu;
    float rs = rsqrtf(var + 1e-5f);
    for (int c = threadIdx.x; c < DM; c += 256) {
        float v = (row[c] - mu) * rs * gam[c] + bet[c];
        g_X2[(size_t)m * DM + c] = v;
        g_X2[(size_t)(4096 + m) * DM + (DM - 1 - c)] = v;
    }
}

/* ---------------- 6. causal + anti-causal depthwise conv1d + SiLU ------- */
__global__ __launch_bounds__(256) void conv1d_k(const float* __restrict__ cw,
                                                const float* __restrict__ cb) {
    __shared__ float s[32][71];
    __shared__ float sw[32][4];
    __shared__ float sb[32];
    int b = blockIdx.z, d0 = blockIdx.y * 32, t0 = blockIdx.x * 64;
    int tid = threadIdx.x;
    if (tid < 128) sw[tid >> 2][tid & 3] = cw[(d0 + (tid >> 2)) * 4 + (tid & 3)];
    if (tid < 32)  sb[tid] = cb[d0 + tid];
    for (int e = tid; e < 32 * 70; e += 256) {
        int dd = e & 31, tt = e >> 5;
        int t = t0 - 3 + tt;
        float v = 0.f;
        if (t >= 0 && t < SEQL) v = g_xz[((size_t)(b * SEQL + t)) * (2*DI) + d0 + dd];
        s[dd][tt] = v;
    }
    __syncthreads();
    int tt = tid & 63, dg = tid >> 6;
    for (int dl = dg; dl < 32; dl += 4) {
        float w0 = sw[dl][0], w1 = sw[dl][1], w2 = sw[dl][2], w3 = sw[dl][3], bb = sb[dl];
        float f = w0*s[dl][tt]   + w1*s[dl][tt+1] + w2*s[dl][tt+2] + w3*s[dl][tt+3] + bb;
        float g = w0*s[dl][tt+6] + w1*s[dl][tt+5] + w2*s[dl][tt+4] + w3*s[dl][tt+3] + bb;
        size_t o = ((size_t)(b * DI + d0 + dl)) * SEQL + t0 + tt;
        g_xmf[o] = f / (1.f + __expf(-f));
        g_xmb[o] = g / (1.f + __expf(-g));
    }
}

/* ---------------- 10. selective scan (fwd + bwd) ------------------------ */
__global__ __launch_bounds__(256) void scan_k(const float* __restrict__ A_log) {
    __shared__ float4 shbc[32][32];
    int dir = blockIdx.z, b = blockIdx.y;
    int wid = threadIdx.x >> 5, lane = threadIdx.x & 31;
    int d = blockIdx.x * 8 + wid;
    const float* dt = (dir ? g_dtb : g_dtf) + ((size_t)(b*DI + d)) * SEQL;
    const float* xm = (dir ? g_xmb : g_xmf) + ((size_t)(b*DI + d)) * SEQL;
    const float* xp = (dir ? g_xpb : g_xpf) + (size_t)b * SEQL * XPW;
    float* y = (dir ? g_yb : g_yf) + ((size_t)(b*DI + d)) * SEQL;
    const float L2E = 1.4426950408889634f;
    float A1 = -__expf(A_log[d*DS + lane])       * L2E;
    float A2 = -__expf(A_log[d*DS + 32 + lane])  * L2E;
    float h1 = 0.f, h2 = 0.f;
    for (int s0 = 0; s0 < SEQL; s0 += 32) {
        __syncthreads();
        for (int e = threadIdx.x; e < 1024; e += 256) {
            int r = e >> 5, n = e & 31;
            int t = dir ? (SEQL - 1 - (s0 + r)) : (s0 + r);
            const float* p = xp + (size_t)t * XPW;
            shbc[r][n] = make_float4(p[48 + n], p[80 + n], p[112 + n], p[144 + n]);
        }
        int tl = dir ? (SEQL - 1 - (s0 + lane)) : (s0 + lane);
        float dtv_b = dt[tl];
        float xv_b  = xm[tl];
        __syncthreads();
        float ykeep = 0.f;
        #pragma unroll 8
        for (int j = 0; j < 32; j++) {
            float dtv = __shfl_sync(~0u, dtv_b, j);
            float xv  = __shfl_sync(~0u, xv_b, j);
            float4 bc = shbc[j][lane];
            float e1, e2;
            asm("ex2.approx.f32 %0, %1;" : "=f"(e1) : "f"(dtv * A1));
            asm("ex2.approx.f32 %0, %1;" : "=f"(e2) : "f"(dtv * A2));
            float uu = dtv * xv;
            h1 = e1 * h1 + uu * bc.x;
            h2 = e2 * h2 + uu * bc.y;
            float p = h1 * bc.z + h2 * bc.w;
            #pragma unroll
            for (int o = 16; o; o >>= 1) p += __shfl_xor_sync(~0u, p, o);
            if (j == lane) ykeep = p;
        }
        y[dir ? (SEQL - 1 - s0 - lane) : (s0 + lane)] = ykeep;
    }
}

/* ---------------- 11. combine dirs + gate, transpose to token-major ----- */
__global__ void combine_k(const float* __restrict__ Dskip) {
    __shared__ float s[32][33];
    int b = blockIdx.z, d0 = blockIdx.y * 32, t0 = blockIdx.x * 32;
    int tx = threadIdx.x, ty = threadIdx.y;     /* 32 x 8 */
    #pragma unroll
    for (int i = 0; i < 4; i++) {
        int d = d0 + ty + i*8;
        size_t I = ((size_t)(b * DI + d)) * SEQL + t0 + tx;
        float v = g_yf[I] + g_yb[I] + Dskip[d] * (g_xmf[I] + g_xmb[I]);
        s[ty + i*8][tx] = v;
    }
    __syncthreads();
    #pragma unroll
    for (int i = 0; i < 4; i++) {
        int t = t0 + ty + i*8;
        int d = d0 + tx;
        float z = g_xz[((size_t)(b * SEQL + t)) * (2*DI) + DI + d];
        float sz = z / (1.f + __expf(-z));
        g_u[((size_t)(b * SEQL + t)) * DI + d] = s[tx][ty + i*8] * sz;
    }
}

/* ---------------- 13. final: average 4 directions ----------------------- */
__global__ void final_k(float* __restrict__ out) {
    int i = blockIdx.x * 256 + threadIdx.x;
    if (i >= 2 * SEQL * DM) return;
    int c = i % DM;
    size_t ml = (size_t)(i / DM);
    out[i] = 0.25f * (g_v[ml * DM + c] +
                      g_v[(ml + (size_t)2 * SEQL) * DM + (DM - 1 - c)]);
}

/* ------------------------------------------------------------------------ */
extern "C" void kernel_launch(void* const* d_in, const int* in_sizes, int n_in,
                              void* d_out, int out_size) {
    const float* x        = (const float*)d_in[0];
    const float* bn_gamma = (const float*)d_in[1];
    const float* bn_beta  = (const float*)d_in[2];
    const float* bn_mean  = (const float*)d_in[3];
    const float* bn_var   = (const float*)d_in[4];
    const float* dw_w     = (const float*)d_in[5];
    const float* pw_w     = (const float*)d_in[6];
    const float* ln_gamma = (const float*)d_in[7];
    const float* ln_beta  = (const float*)d_in[8];
    const float* W_in     = (const float*)d_in[9];
    const float* conv_w   = (const float*)d_in[10];
    const float* conv_b   = (const float*)d_in[11];
    const float* W_x      = (const float*)d_in[12];
    const float* W_dt     = (const float*)d_in[13];
    const float* b_dt     = (const float*)d_in[14];
    const float* A_log    = (const float*)d_in[15];
    const float* D_skip   = (const float*)d_in[16];
    const float* W_out    = (const float*)d_in[17];
    float* out            = (float*)d_out;

    float *p_act1, *p_hdw, *p_h2, *p_X2, *p_xz, *p_xmf, *p_xmb, *p_xpf, *p_xpb,
          *p_dttmf, *p_dttmb, *p_dtf, *p_dtb, *p_u, *p_v;
    cudaGetSymbolAddress((void**)&p_act1, g_act1);
    cudaGetSymbolAddress((void**)&p_hdw,  g_hdw);
    cudaGetSymbolAddress((void**)&p_h2,   g_h2);
    cudaGetSymbolAddress((void**)&p_X2,   g_X2);
    cudaGetSymbolAddress((void**)&p_xz,   g_xz);
    cudaGetSymbolAddress((void**)&p_xmf,  g_xmf);
    cudaGetSymbolAddress((void**)&p_xmb,  g_xmb);
    cudaGetSymbolAddress((void**)&p_xpf,  g_xpf);
    cudaGetSymbolAddress((void**)&p_xpb,  g_xpb);
    cudaGetSymbolAddress((void**)&p_dttmf, g_dttmf);
    cudaGetSymbolAddress((void**)&p_dttmb, g_dttmb);
    cudaGetSymbolAddress((void**)&p_dtf,  g_dtf);
    cudaGetSymbolAddress((void**)&p_dtb,  g_dtb);
    cudaGetSymbolAddress((void**)&p_u,    g_u);
    cudaGetSymbolAddress((void**)&p_v,    g_v);

    cudaFuncSetAttribute(mma_gemm_k<0,false>, cudaFuncAttributeMaxDynamicSharedMemorySize, SM_TOTAL);
    cudaFuncSetAttribute(mma_gemm_k<1,false>, cudaFuncAttributeMaxDynamicSharedMemorySize, SM_TOTAL);
    cudaFuncSetAttribute(mma_gemm_k<2,true>,  cudaFuncAttributeMaxDynamicSharedMemorySize, SM_TOTAL);

    /* front-end */
    bn_lrelu_k<<<12288, 256>>>(x, bn_gamma, bn_beta, bn_mean, bn_var);
    dwconv_k<<<12288, 256>>>(dw_w);
    /* hdw [b,c,t] -> token-major in g_act1 */
    transpose_g<<<dim3(64, 24, 2), dim3(32, 8)>>>(p_hdw, p_act1, DM, SEQL);
    /* pointwise conv: [4096,768] x [768,768]^T, leaky-relu epilogue */
    mma_gemm_k<1,false><<<dim3(6, 32), 256, SM_TOTAL>>>(p_act1, pw_w, p_h2, nullptr,
                                                        4096, DM, DM, DM);
    ln_k<<<2*SEQL, 256>>>(ln_gamma, ln_beta);
    /* in_proj: [8192,768] x [3072,768]^T */
    mma_gemm_k<0,false><<<dim3(24, 64), 256, SM_TOTAL>>>(p_X2, W_in, p_xz, nullptr,
                                                         MTOK, 2*DI, DM, DM);
    conv1d_k<<<dim3(32, 48, NB), 256>>>(conv_w, conv_b);
    /* xm [b,d,t] -> token-major (reuse dttm buffers) */
    transpose_g<<<dim3(64, 48, NB), dim3(32, 8)>>>(p_xmf, p_dttmf, DI, SEQL);
    transpose_g<<<dim3(64, 48, NB), dim3(32, 8)>>>(p_xmb, p_dttmb, DI, SEQL);
    /* x_proj: [8192,1536] x [176,1536]^T */
    mma_gemm_k<0,false><<<dim3(2, 64), 256, SM_TOTAL>>>(p_dttmf, W_x, p_xpf, nullptr,
                                                        MTOK, XPW, DI, DI);
    mma_gemm_k<0,false><<<dim3(2, 64), 256, SM_TOTAL>>>(p_dttmb, W_x, p_xpb, nullptr,
                                                        MTOK, XPW, DI, DI);
    /* dt proj + softplus: [8192,48(pad)] x [1536,48]^T */
    mma_gemm_k<2,true><<<dim3(12, 64), 256, SM_TOTAL>>>(p_xpf, W_dt, p_dttmf, b_dt,
                                                        MTOK, DI, DTR, XPW);
    mma_gemm_k<2,true><<<dim3(12, 64), 256, SM_TOTAL>>>(p_xpb, W_dt, p_dttmb, b_dt,
                                                        MTOK, DI, DTR, XPW);
    /* dt token-major -> [b,d,t] */
    transpose_g<<<dim3(48, 64, NB), dim3(32, 8)>>>(p_dttmf, p_dtf, SEQL, DI);
    transpose_g<<<dim3(48, 64, NB), dim3(32, 8)>>>(p_dttmb, p_dtb, SEQL, DI);
    /* selective scan */
    scan_k<<<dim3(DI/8, NB, 2), 256>>>(A_log);
    combine_k<<<dim3(64, 48, NB), dim3(32, 8)>>>(D_skip);
    /* out_proj: [8192,1536] x [768,1536]^T */
    mma_gemm_k<0,false><<<dim3(6, 64), 256, SM_TOTAL>>>(p_u, W_out, p_v, nullptr,
                                                        MTOK, DM, DI, DI);
    final_k<<<12288, 256>>>(out);
    (void)in_sizes; (void)n_in; (void)out_size;
}

// round 6
// speedup vs baseline: 1.6910x; 1.6910x over previous
#include <cuda_runtime.h>
#include <cuda_fp16.h>
#include <mma.h>
#include <cstdint>
#include <cstdio>

using namespace nvcuda;

#define DM   768
#define DI   1536
#define DS   64
#define DTR  48
#define SEQL 2048
#define NB   4            /* effective batch: 2 orig x 2 channel-flip */
#define MTOK (NB*SEQL)    /* 8192 token rows */
#define XPW  176          /* DTR + 2*DS */

/* ---------------- scratch (static device globals; no allocation) -------- */
__device__ float g_act1[2*DM*SEQL];   /* also reused as hdw^T */
__device__ float g_hdw [2*DM*SEQL];
__device__ float g_h2  [2*SEQL*DM];
__device__ float g_X2  [MTOK*DM];
__device__ float g_xz  [MTOK*2*DI];
__device__ float g_xmf [NB*DI*SEQL];
__device__ float g_xmb [NB*DI*SEQL];
__device__ float g_xpf [MTOK*XPW];
__device__ float g_xpb [MTOK*XPW];
__device__ float g_dttmf[MTOK*DI];    /* reused first as xm_f token-major */
__device__ float g_dttmb[MTOK*DI];    /* reused first as xm_b token-major */
__device__ float g_dtf [NB*DI*SEQL];
__device__ float g_dtb [NB*DI*SEQL];
__device__ float g_yf  [NB*DI*SEQL];
__device__ float g_yb  [NB*DI*SEQL];
__device__ float g_u   [MTOK*DI];
__device__ float g_v   [MTOK*DM];
/* fp16 hi/lo split scratch (A operand up to MTOK*DI, W up to 2*DI*DM) */
__device__ __half g_Ah[MTOK*DI];
__device__ __half g_Al[MTOK*DI];
__device__ __half g_Wh[2*DI*DM];
__device__ __half g_Wl[2*DI*DM];

/* ======================= small helpers ================================= */
__device__ __forceinline__ uint32_t smem_u32(const void* p) {
    uint32_t a;
    asm("{ .reg .u64 t; cvta.to.shared.u64 t, %1; cvt.u32.u64 %0, t; }" : "=r"(a) : "l"(p));
    return a;
}
__device__ __forceinline__ void cpa16(uint32_t dst, const void* src) {
    asm volatile("cp.async.cg.shared.global [%0], [%1], 16;\n" :: "r"(dst), "l"(src));
}
#define CP_COMMIT() asm volatile("cp.async.commit_group;\n" ::: "memory")
#define CP_WAIT(n)  asm volatile("cp.async.wait_group %0;\n" :: "n"(n) : "memory")

/* ---------------- fp32 -> (hi, lo) fp16 split --------------------------- */
__global__ void split_k(const float* __restrict__ in, __half* __restrict__ hi,
                        __half* __restrict__ lo, int n2) {
    int i = blockIdx.x * 256 + threadIdx.x;
    if (i >= n2) return;
    float2 v = ((const float2*)in)[i];
    __half hx = __float2half_rn(v.x), hy = __float2half_rn(v.y);
    ((__half2*)hi)[i] = __halves2half2(hx, hy);
    ((__half2*)lo)[i] = __halves2half2(__float2half_rn(v.x - __half2float(hx)),
                                       __float2half_rn(v.y - __half2float(hy)));
}

/* ================= split-fp16 mma.sync GEMM ============================
   C[m,n] = sum_k A[m,k] * W[n,k],  A = Ah + Al, W = Wh + Wl (fp16 pairs).
   acc += Ah*Wh + Ah*Wl + Al*Wh  (Al*Wl ~2^-22, dropped) -> ~fp32 accuracy.
   Ah/Al: row-major [M,K] halves (row stride lda); Wh/Wl: [N,K] halves.
   Block tile 128(M) x 128(N) x 32(K); 8 warps, each 64x32 (4x2 frags).
   EPI: 0 none, 1 leaky-relu, 2 softplus(x + bias[n]).
   KPAD: K not multiple of 32 -> zero-fill pad (8-half granularity).       */
#define HST 40                        /* smem row stride, halves (80 B) */
#define TILE_B 10240                  /* one 128xHST half tile, bytes */
#define STG 132                       /* epilogue staging stride, floats */
#define SM_TOTAL (8*TILE_B)           /* 81920 bytes */

typedef wmma::fragment<wmma::matrix_a,16,16,16,__half,wmma::row_major> HA;
typedef wmma::fragment<wmma::matrix_b,16,16,16,__half,wmma::col_major> HB;

template<int EPI, bool KPAD>
__global__ __launch_bounds__(256, 2) void hmma_gemm_k(
    const __half* __restrict__ Ah, const __half* __restrict__ Al,
    const __half* __restrict__ Wh, const __half* __restrict__ Wl,
    float* __restrict__ C, const float* __restrict__ bias,
    int M, int N, int K, int lda)
{
    extern __shared__ char smc[];
    float* smf = (float*)smc;
    int tid = threadIdx.x, wid = tid >> 5;
    int m0 = blockIdx.y * 128, n0 = blockIdx.x * 128;
    int wm = (wid & 1) * 64, wn = (wid >> 1) * 32;
    uint32_t sbase = smem_u32(smc);

    wmma::fragment<wmma::accumulator,16,16,16,float> acc[4][2];
    #pragma unroll
    for (int i = 0; i < 4; i++)
        #pragma unroll
        for (int j = 0; j < 2; j++) wmma::fill_fragment(acc[i][j], 0.f);

    const int NKB = (K + 31) / 32;

    /* prefetch K-block kb into stage kb&1: 4 arrays x 128 rows x 4 chunks */
    auto prefetch = [&](int kb) {
        int k0 = kb * 32, s = kb & 1;
        int soff = s * (4 * TILE_B);
        #pragma unroll
        for (int i = 0; i < 8; i++) {
            int e = tid + (i << 8);
            int arr = e >> 9, r = (e >> 2) & 127, q = e & 3;
            int off = soff + arr * TILE_B + r * 80 + q * 16;
            bool ok = (!KPAD || (k0 + q * 8 < K));
            const __half* src;
            if (arr < 2) {
                src = (arr == 0 ? Ah : Al) + (long)(m0 + r) * lda + k0 + q * 8;
            } else {
                src = (arr == 2 ? Wh : Wl) + (long)(n0 + r) * K + k0 + q * 8;
                ok = ok && (n0 + r < N);
            }
            if (ok) cpa16(sbase + off, src);
            else    *(float4*)(smc + off) = make_float4(0.f, 0.f, 0.f, 0.f);
        }
        CP_COMMIT();
    };

    prefetch(0);
    for (int kb = 0; kb < NKB; kb++) {
        int s = kb & 1;
        if (kb + 1 < NKB) { prefetch(kb + 1); CP_WAIT(1); }
        else              { CP_WAIT(0); }
        __syncthreads();
        const char* st = smc + s * (4 * TILE_B);
        const __half* pAh = (const __half*)(st);
        const __half* pAl = (const __half*)(st + TILE_B);
        const __half* pBh = (const __half*)(st + 2*TILE_B);
        const __half* pBl = (const __half*)(st + 3*TILE_B);
        #pragma unroll
        for (int ks = 0; ks < 2; ks++) {
            HB bh[2], bl[2];
            #pragma unroll
            for (int j = 0; j < 2; j++) {
                wmma::load_matrix_sync(bh[j], pBh + (wn + j*16) * HST + ks*16, HST);
                wmma::load_matrix_sync(bl[j], pBl + (wn + j*16) * HST + ks*16, HST);
            }
            #pragma unroll
            for (int i = 0; i < 4; i++) {
                HA ah, al;
                wmma::load_matrix_sync(ah, pAh + (wm + i*16) * HST + ks*16, HST);
                wmma::load_matrix_sync(al, pAl + (wm + i*16) * HST + ks*16, HST);
                #pragma unroll
                for (int j = 0; j < 2; j++) {
                    wmma::mma_sync(acc[i][j], ah, bh[j], acc[i][j]);
                    wmma::mma_sync(acc[i][j], ah, bl[j], acc[i][j]);
                    wmma::mma_sync(acc[i][j], al, bh[j], acc[i][j]);
                }
            }
        }
        __syncthreads();
    }

    /* stage C through shared for coalesced, epilogued global stores */
    #pragma unroll
    for (int i = 0; i < 4; i++)
        #pragma unroll
        for (int j = 0; j < 2; j++)
            wmma::store_matrix_sync(smf + (wm + i*16) * STG + wn + j*16,
                                    acc[i][j], STG, wmma::mem_row_major);
    __syncthreads();
    #pragma unroll
    for (int it = 0; it < 16; it++) {
        int e = tid + (it << 8);
        int r = e >> 5, c4 = (e & 31) << 2;
        int n = n0 + c4;
        if (n < N) {
            float4 v = *(float4*)(smf + r * STG + c4);
            if (EPI == 1) {
                v.x = v.x > 0.f ? v.x : 0.01f * v.x;
                v.y = v.y > 0.f ? v.y : 0.01f * v.y;
                v.z = v.z > 0.f ? v.z : 0.01f * v.z;
                v.w = v.w > 0.f ? v.w : 0.01f * v.w;
            } else if (EPI == 2) {
                v.x += bias[n];     v.y += bias[n + 1];
                v.z += bias[n + 2]; v.w += bias[n + 3];
                v.x = (v.x > 20.f) ? v.x : log1pf(__expf(v.x));
                v.y = (v.y > 20.f) ? v.y : log1pf(__expf(v.y));
                v.z = (v.z > 20.f) ? v.z : log1pf(__expf(v.z));
                v.w = (v.w > 20.f) ? v.w : log1pf(__expf(v.w));
            }
            *(float4*)(C + (long)(m0 + r) * N + n) = v;
        }
    }
}

/* ---------------- 1. BatchNorm3d(eval) + LeakyReLU ---------------------- */
__global__ void bn_lrelu_k(const float* __restrict__ x, const float* __restrict__ g,
                           const float* __restrict__ be, const float* __restrict__ mu,
                           const float* __restrict__ var) {
    int i = blockIdx.x * 256 + threadIdx.x;
    if (i >= 2*DM*SEQL) return;
    int c = (i / SEQL) % DM;
    float v = (x[i] - mu[c]) * rsqrtf(var[c] + 1e-5f) * g[c] + be[c];
    g_act1[i] = v > 0.f ? v : 0.01f * v;
}

/* ---------------- 2. depthwise conv3d 3x3x3 SAME ------------------------ */
__global__ void dwconv_k(const float* __restrict__ wt) {
    int i = blockIdx.x * 256 + threadIdx.x;
    if (i >= 2*DM*SEQL) return;
    int w = i & 15, h = (i >> 4) & 15, d = (i >> 8) & 7;
    int c = (i >> 11) % DM;
    int b = i / (DM * SEQL);
    const float* wp = wt + c * 27;
    const float* ip = g_act1 + (size_t)(b*DM + c) * SEQL;
    float acc = 0.f;
    #pragma unroll
    for (int kd = 0; kd < 3; kd++) {
        int dd = d + kd - 1; if (dd < 0 || dd > 7) continue;
        #pragma unroll
        for (int kh = 0; kh < 3; kh++) {
            int hh = h + kh - 1; if (hh < 0 || hh > 15) continue;
            #pragma unroll
            for (int kw = 0; kw < 3; kw++) {
                int ww = w + kw - 1; if (ww < 0 || ww > 15) continue;
                acc += wp[kd*9 + kh*3 + kw] * ip[dd*256 + hh*16 + ww];
            }
        }
    }
    g_hdw[i] = acc;
}

/* ---------------- generic 32x32 transpose ------------------------------- */
/* in[(b*R + r)*Cc + c]  ->  out[(b*Cc + c)*R + r]                          */
__global__ void transpose_g(const float* __restrict__ in, float* __restrict__ out,
                            int R, int Cc) {
    __shared__ float s[32][33];
    int b = blockIdx.z, r0 = blockIdx.y * 32, c0 = blockIdx.x * 32;
    int tx = threadIdx.x, ty = threadIdx.y;     /* 32 x 8 */
    #pragma unroll
    for (int i = 0; i < 4; i++)
        s[ty + i*8][tx] = in[((long)(b * R + r0 + ty + i*8)) * Cc + c0 + tx];
    __syncthreads();
    #pragma unroll
    for (int i = 0; i < 4; i++)
        out[((long)(b * Cc + c0 + ty + i*8)) * R + r0 + tx] = s[tx][ty + i*8];
}

/* ---------------- 4. LayerNorm over channels; emit X2 (orig + c-flip) --- */
__global__ void ln_k(const float* __restrict__ gam, const float* __restrict__ bet) {
    int m = blockIdx.x;                 /* token 0..4095 */
    __shared__ float red[16];
    const float* row = g_h2 + (size_t)m * DM;
    float s = 0.f, s2 = 0.f;
    for (int c = threadIdx.x; c < DM; c += 256) { float v = row[c]; s += v; s2 += v*v; }
    #pragma unroll
    for (int o = 16; o; o >>= 1) {
        s  += __shfl_xor_sync(~0u, s, o);
        s2 += __shfl_xor_sync(~0u, s2, o);
    }
    int wid = threadIdx.x >> 5, ln = threadIdx.x & 31;
    if (ln == 0) { red[wid] = s; red[8 + wid] = s2; }
    __syncthreads();
    float ts = 0.f, ts2 = 0.f;
    #pragma unroll
    for (int i = 0; i < 8; i++) { ts += red[i]; ts2 += red[8 + i]; }
    float mu = ts / 768.f;
    float var = ts2 / 768.f - mu * mu;
    float rs = rsqrtf(var + 1e-5f);
    for (int c = threadIdx.x; c < DM; c += 256) {
        float v = (row[c] - mu) * rs * gam[c] + bet[c];
        g_X2[(size_t)m * DM + c] = v;
        g_X2[(size_t)(4096 + m) * DM + (DM - 1 - c)] = v;
    }
}

/* ---------------- 6. causal + anti-causal depthwise conv1d + SiLU ------- */
__global__ __launch_bounds__(256) void conv1d_k(const float* __restrict__ cw,
                                                const float* __restrict__ cb) {
    __shared__ float s[32][71];
    __shared__ float sw[32][4];
    __shared__ float sb[32];
    int b = blockIdx.z, d0 = blockIdx.y * 32, t0 = blockIdx.x * 64;
    int tid = threadIdx.x;
    if (tid < 128) sw[tid >> 2][tid & 3] = cw[(d0 + (tid >> 2)) * 4 + (tid & 3)];
    if (tid < 32)  sb[tid] = cb[d0 + tid];
    for (int e = tid; e < 32 * 70; e += 256) {
        int dd = e & 31, tt = e >> 5;
        int t = t0 - 3 + tt;
        float v = 0.f;
        if (t >= 0 && t < SEQL) v = g_xz[((size_t)(b * SEQL + t)) * (2*DI) + d0 + dd];
        s[dd][tt] = v;
    }
    __syncthreads();
    int tt = tid & 63, dg = tid >> 6;
    for (int dl = dg; dl < 32; dl += 4) {
        float w0 = sw[dl][0], w1 = sw[dl][1], w2 = sw[dl][2], w3 = sw[dl][3], bb = sb[dl];
        float f = w0*s[dl][tt]   + w1*s[dl][tt+1] + w2*s[dl][tt+2] + w3*s[dl][tt+3] + bb;
        float g = w0*s[dl][tt+6] + w1*s[dl][tt+5] + w2*s[dl][tt+4] + w3*s[dl][tt+3] + bb;
        size_t o = ((size_t)(b * DI + d0 + dl)) * SEQL + t0 + tt;
        g_xmf[o] = f / (1.f + __expf(-f));
        g_xmb[o] = g / (1.f + __expf(-g));
    }
}

/* ---------------- 10. selective scan (fwd + bwd) ------------------------ */
__global__ __launch_bounds__(256) void scan_k(const float* __restrict__ A_log) {
    __shared__ float4 shbc[32][32];
    int dir = blockIdx.z, b = blockIdx.y;
    int wid = threadIdx.x >> 5, lane = threadIdx.x & 31;
    int d = blockIdx.x * 8 + wid;
    const float* dt = (dir ? g_dtb : g_dtf) + ((size_t)(b*DI + d)) * SEQL;
    const float* xm = (dir ? g_xmb : g_xmf) + ((size_t)(b*DI + d)) * SEQL;
    const float* xp = (dir ? g_xpb : g_xpf) + (size_t)b * SEQL * XPW;
    float* y = (dir ? g_yb : g_yf) + ((size_t)(b*DI + d)) * SEQL;
    const float L2E = 1.4426950408889634f;
    float A1 = -__expf(A_log[d*DS + lane])       * L2E;
    float A2 = -__expf(A_log[d*DS + 32 + lane])  * L2E;
    float h1 = 0.f, h2 = 0.f;
    for (int s0 = 0; s0 < SEQL; s0 += 32) {
        __syncthreads();
        for (int e = threadIdx.x; e < 1024; e += 256) {
            int r = e >> 5, n = e & 31;
            int t = dir ? (SEQL - 1 - (s0 + r)) : (s0 + r);
            const float* p = xp + (size_t)t * XPW;
            shbc[r][n] = make_float4(p[48 + n], p[80 + n], p[112 + n], p[144 + n]);
        }
        int tl = dir ? (SEQL - 1 - (s0 + lane)) : (s0 + lane);
        float dtv_b = dt[tl];
        float xv_b  = xm[tl];
        __syncthreads();
        float ykeep = 0.f;
        #pragma unroll 8
        for (int j = 0; j < 32; j++) {
            float dtv = __shfl_sync(~0u, dtv_b, j);
            float xv  = __shfl_sync(~0u, xv_b, j);
            float4 bc = shbc[j][lane];
            float e1, e2;
            asm("ex2.approx.f32 %0, %1;" : "=f"(e1) : "f"(dtv * A1));
            asm("ex2.approx.f32 %0, %1;" : "=f"(e2) : "f"(dtv * A2));
            float uu = dtv * xv;
            h1 = e1 * h1 + uu * bc.x;
            h2 = e2 * h2 + uu * bc.y;
            float p = h1 * bc.z + h2 * bc.w;
            #pragma unroll
            for (int o = 16; o; o >>= 1) p += __shfl_xor_sync(~0u, p, o);
            if (j == lane) ykeep = p;
        }
        y[dir ? (SEQL - 1 - s0 - lane) : (s0 + lane)] = ykeep;
    }
}

/* ---------------- 11. combine dirs + gate, transpose to token-major ----- */
__global__ void combine_k(const float* __restrict__ Dskip) {
    __shared__ float s[32][33];
    int b = blockIdx.z, d0 = blockIdx.y * 32, t0 = blockIdx.x * 32;
    int tx = threadIdx.x, ty = threadIdx.y;     /* 32 x 8 */
    #pragma unroll
    for (int i = 0; i < 4; i++) {
        int d = d0 + ty + i*8;
        size_t I = ((size_t)(b * DI + d)) * SEQL + t0 + tx;
        float v = g_yf[I] + g_yb[I] + Dskip[d] * (g_xmf[I] + g_xmb[I]);
        s[ty + i*8][tx] = v;
    }
    __syncthreads();
    #pragma unroll
    for (int i = 0; i < 4; i++) {
        int t = t0 + ty + i*8;
        int d = d0 + tx;
        float z = g_xz[((size_t)(b * SEQL + t)) * (2*DI) + DI + d];
        float sz = z / (1.f + __expf(-z));
        g_u[((size_t)(b * SEQL + t)) * DI + d] = s[tx][ty + i*8] * sz;
    }
}

/* ---------------- 13. final: average 4 directions ----------------------- */
__global__ void final_k(float* __restrict__ out) {
    int i = blockIdx.x * 256 + threadIdx.x;
    if (i >= 2 * SEQL * DM) return;
    int c = i % DM;
    size_t ml = (size_t)(i / DM);
    out[i] = 0.25f * (g_v[ml * DM + c] +
                      g_v[(ml + (size_t)2 * SEQL) * DM + (DM - 1 - c)]);
}

/* ------------------------------------------------------------------------ */
static inline void split_launch(const float* p, __half* h, __half* l, long n) {
    int n2 = (int)(n / 2);
    split_k<<<(n2 + 255) / 256, 256>>>(p, h, l, n2);
}

extern "C" void kernel_launch(void* const* d_in, const int* in_sizes, int n_in,
                              void* d_out, int out_size) {
    const float* x        = (const float*)d_in[0];
    const float* bn_gamma = (const float*)d_in[1];
    const float* bn_beta  = (const float*)d_in[2];
    const float* bn_mean  = (const float*)d_in[3];
    const float* bn_var   = (const float*)d_in[4];
    const float* dw_w     = (const float*)d_in[5];
    const float* pw_w     = (const float*)d_in[6];
    const float* ln_gamma = (const float*)d_in[7];
    const float* ln_beta  = (const float*)d_in[8];
    const float* W_in     = (const float*)d_in[9];
    const float* conv_w   = (const float*)d_in[10];
    const float* conv_b   = (const float*)d_in[11];
    const float* W_x      = (const float*)d_in[12];
    const float* W_dt     = (const float*)d_in[13];
    const float* b_dt     = (const float*)d_in[14];
    const float* A_log    = (const float*)d_in[15];
    const float* D_skip   = (const float*)d_in[16];
    const float* W_out    = (const float*)d_in[17];
    float* out            = (float*)d_out;

    float *p_act1, *p_hdw, *p_h2, *p_X2, *p_xz, *p_xmf, *p_xmb, *p_xpf, *p_xpb,
          *p_dttmf, *p_dttmb, *p_dtf, *p_dtb, *p_u, *p_v;
    __half *p_Ah, *p_Al, *p_Wh, *p_Wl;
    cudaGetSymbolAddress((void**)&p_act1, g_act1);
    cudaGetSymbolAddress((void**)&p_hdw,  g_hdw);
    cudaGetSymbolAddress((void**)&p_h2,   g_h2);
    cudaGetSymbolAddress((void**)&p_X2,   g_X2);
    cudaGetSymbolAddress((void**)&p_xz,   g_xz);
    cudaGetSymbolAddress((void**)&p_xmf,  g_xmf);
    cudaGetSymbolAddress((void**)&p_xmb,  g_xmb);
    cudaGetSymbolAddress((void**)&p_xpf,  g_xpf);
    cudaGetSymbolAddress((void**)&p_xpb,  g_xpb);
    cudaGetSymbolAddress((void**)&p_dttmf, g_dttmf);
    cudaGetSymbolAddress((void**)&p_dttmb, g_dttmb);
    cudaGetSymbolAddress((void**)&p_dtf,  g_dtf);
    cudaGetSymbolAddress((void**)&p_dtb,  g_dtb);
    cudaGetSymbolAddress((void**)&p_u,    g_u);
    cudaGetSymbolAddress((void**)&p_v,    g_v);
    cudaGetSymbolAddress((void**)&p_Ah,   g_Ah);
    cudaGetSymbolAddress((void**)&p_Al,   g_Al);
    cudaGetSymbolAddress((void**)&p_Wh,   g_Wh);
    cudaGetSymbolAddress((void**)&p_Wl,   g_Wl);

    cudaFuncSetAttribute(hmma_gemm_k<0,false>, cudaFuncAttributeMaxDynamicSharedMemorySize, SM_TOTAL);
    cudaFuncSetAttribute(hmma_gemm_k<1,false>, cudaFuncAttributeMaxDynamicSharedMemorySize, SM_TOTAL);
    cudaFuncSetAttribute(hmma_gemm_k<2,true>,  cudaFuncAttributeMaxDynamicSharedMemorySize, SM_TOTAL);

    /* front-end */
    bn_lrelu_k<<<12288, 256>>>(x, bn_gamma, bn_beta, bn_mean, bn_var);
    dwconv_k<<<12288, 256>>>(dw_w);
    /* hdw [b,c,t] -> token-major in g_act1 */
    transpose_g<<<dim3(64, 24, 2), dim3(32, 8)>>>(p_hdw, p_act1, DM, SEQL);
    /* pointwise conv: [4096,768] x [768,768]^T, leaky-relu epilogue */
    split_launch(p_act1, p_Ah, p_Al, (long)4096*DM);
    split_launch(pw_w,   p_Wh, p_Wl, (long)DM*DM);
    hmma_gemm_k<1,false><<<dim3(6, 32), 256, SM_TOTAL>>>(p_Ah, p_Al, p_Wh, p_Wl,
                                                         p_h2, nullptr, 4096, DM, DM, DM);
    ln_k<<<2*SEQL, 256>>>(ln_gamma, ln_beta);
    /* in_proj: [8192,768] x [3072,768]^T */
    split_launch(p_X2, p_Ah, p_Al, (long)MTOK*DM);
    split_launch(W_in, p_Wh, p_Wl, (long)2*DI*DM);
    hmma_gemm_k<0,false><<<dim3(24, 64), 256, SM_TOTAL>>>(p_Ah, p_Al, p_Wh, p_Wl,
                                                          p_xz, nullptr, MTOK, 2*DI, DM, DM);
    conv1d_k<<<dim3(32, 48, NB), 256>>>(conv_w, conv_b);
    /* xm [b,d,t] -> token-major (reuse dttm buffers) */
    transpose_g<<<dim3(64, 48, NB), dim3(32, 8)>>>(p_xmf, p_dttmf, DI, SEQL);
    transpose_g<<<dim3(64, 48, NB), dim3(32, 8)>>>(p_xmb, p_dttmb, DI, SEQL);
    /* x_proj: [8192,1536] x [176,1536]^T */
    split_launch(W_x, p_Wh, p_Wl, (long)XPW*DI);
    split_launch(p_dttmf, p_Ah, p_Al, (long)MTOK*DI);
    hmma_gemm_k<0,false><<<dim3(2, 64), 256, SM_TOTAL>>>(p_Ah, p_Al, p_Wh, p_Wl,
                                                         p_xpf, nullptr, MTOK, XPW, DI, DI);
    split_launch(p_dttmb, p_Ah, p_Al, (long)MTOK*DI);
    hmma_gemm_k<0,false><<<dim3(2, 64), 256, SM_TOTAL>>>(p_Ah, p_Al, p_Wh, p_Wl,
                                                         p_xpb, nullptr, MTOK, XPW, DI, DI);
    /* dt proj + softplus: [8192,48(pad)] x [1536,48]^T */
    split_launch(W_dt, p_Wh, p_Wl, (long)DI*DTR);
    split_launch(p_xpf, p_Ah, p_Al, (long)MTOK*XPW);
    hmma_gemm_k<2,true><<<dim3(12, 64), 256, SM_TOTAL>>>(p_Ah, p_Al, p_Wh, p_Wl,
                                                         p_dttmf, b_dt, MTOK, DI, DTR, XPW);
    split_launch(p_xpb, p_Ah, p_Al, (long)MTOK*XPW);
    hmma_gemm_k<2,true><<<dim3(12, 64), 256, SM_TOTAL>>>(p_Ah, p_Al, p_Wh, p_Wl,
                                                         p_dttmb, b_dt, MTOK, DI, DTR, XPW);
    /* dt token-major -> [b,d,t] */
    transpose_g<<<dim3(48, 64, NB), dim3(32, 8)>>>(p_dttmf, p_dtf, SEQL, DI);
    transpose_g<<<dim3(48, 64, NB), dim3(32, 8)>>>(p_dttmb, p_dtb, SEQL, DI);
    /* selective scan */
    scan_k<<<dim3(DI/8, NB, 2), 256>>>(A_log);
    combine_k<<<dim3(64, 48, NB), dim3(32, 8)>>>(D_skip);
    /* out_proj: [8192,1536] x [768,1536]^T */
    split_launch(p_u,   p_Ah, p_Al, (long)MTOK*DI);
    split_launch(W_out, p_Wh, p_Wl, (long)DM*DI);
    hmma_gemm_k<0,false><<<dim3(6, 64), 256, SM_TOTAL>>>(p_Ah, p_Al, p_Wh, p_Wl,
                                                         p_v, nullptr, MTOK, DM, DI, DI);
    final_k<<<12288, 256>>>(out);
    (void)in_sizes; (void)n_in; (void)out_size;
}

// round 7
// speedup vs baseline: 1.9508x; 1.1536x over previous
#include <cuda_runtime.h>
#include <cuda_fp16.h>
#include <mma.h>
#include <cstdint>
#include <cstdio>

using namespace nvcuda;

#define DM   768
#define DI   1536
#define DS   64
#define DTR  48
#define SEQL 2048
#define NB   4            /* effective batch: 2 orig x 2 channel-flip */
#define MTOK (NB*SEQL)    /* 8192 token rows */
#define XPW  176          /* DTR + 2*DS */

/* ---------------- scratch (static device globals; no allocation) -------- */
__device__ float g_act1[2*DM*SEQL];
__device__ float g_hdw [2*DM*SEQL];
__device__ float g_h2  [2*SEQL*DM];
__device__ float g_xz  [MTOK*2*DI];
__device__ float g_xmf [NB*DI*SEQL];
__device__ float g_xmb [NB*DI*SEQL];
__device__ float g_xpf [MTOK*XPW];
__device__ float g_xpb [MTOK*XPW];
__device__ float g_dttmf[MTOK*DI];
__device__ float g_dttmb[MTOK*DI];
__device__ float g_dtf [NB*DI*SEQL];
__device__ float g_dtb [NB*DI*SEQL];
__device__ float g_yf  [NB*DI*SEQL];
__device__ float g_yb  [NB*DI*SEQL];
__device__ float g_v   [MTOK*DM];
/* fp16 hi/lo operand scratch */
__device__ __half g_Ah [MTOK*DI];        /* sequentially reused A operand */
__device__ __half g_Al [MTOK*DI];
__device__ __half g_Wh [4500000];        /* all weight halves, offsets below */
__device__ __half g_Wl [4500000];
__device__ __half g_xph[2*MTOK*XPW];     /* xp halves (dir f at 0, b at MTOK*XPW) */
__device__ __half g_xpl[2*MTOK*XPW];

#define OFF_PW  0
#define OFF_IN  (DM*DM)                      /* 589824 */
#define OFF_X   (OFF_IN + 2*DI*DM)           /* +2359296 */
#define OFF_DT  (OFF_X + XPW*DI)             /* +270336 */
#define OFF_OUT (OFF_DT + DI*DTR)            /* +73728 */

/* ======================= small helpers ================================= */
__device__ __forceinline__ uint32_t smem_u32(const void* p) {
    uint32_t a;
    asm("{ .reg .u64 t; cvta.to.shared.u64 t, %1; cvt.u32.u64 %0, t; }" : "=r"(a) : "l"(p));
    return a;
}
__device__ __forceinline__ void cpa16(uint32_t dst, const void* src) {
    asm volatile("cp.async.cg.shared.global [%0], [%1], 16;\n" :: "r"(dst), "l"(src));
}
#define CP_COMMIT() asm volatile("cp.async.commit_group;\n" ::: "memory")
#define CP_WAIT(n)  asm volatile("cp.async.wait_group %0;\n" :: "n"(n) : "memory")

/* ---------------- fp32 -> (hi, lo) fp16 split (weights only) ------------ */
__global__ void split_k(const float* __restrict__ in, __half* __restrict__ hi,
                        __half* __restrict__ lo, int n2) {
    int i = blockIdx.x * 256 + threadIdx.x;
    if (i >= n2) return;
    float2 v = ((const float2*)in)[i];
    __half hx = __float2half_rn(v.x), hy = __float2half_rn(v.y);
    ((__half2*)hi)[i] = __halves2half2(hx, hy);
    ((__half2*)lo)[i] = __halves2half2(__float2half_rn(v.x - __half2float(hx)),
                                       __float2half_rn(v.y - __half2float(hy)));
}

/* ================= split-fp16 mma.sync GEMM ============================
   C[m,n] = sum_k A[m,k] * W[n,k],  A = Ah + Al, W = Wh + Wl (fp16 pairs).
   acc += Ah*Wh + Ah*Wl + Al*Wh  (Al*Wl ~2^-22, dropped) -> ~fp32 accuracy.
   EPI: 0 none, 1 leaky-relu, 2 softplus(x + bias[n]).
   KPAD: K not multiple of 32.  SPLITC: also emit fp16 hi/lo of C.         */
#define HST 40                        /* smem row stride, halves (80 B) */
#define TILE_B 10240                  /* one 128xHST half tile, bytes */
#define STG 132                       /* epilogue staging stride, floats */
#define SM_TOTAL (8*TILE_B)           /* 81920 bytes */

typedef wmma::fragment<wmma::matrix_a,16,16,16,__half,wmma::row_major> HA;
typedef wmma::fragment<wmma::matrix_b,16,16,16,__half,wmma::col_major> HB;

template<int EPI, bool KPAD, bool SPLITC>
__global__ __launch_bounds__(256, 2) void hmma_gemm_k(
    const __half* __restrict__ Ah, const __half* __restrict__ Al,
    const __half* __restrict__ Wh, const __half* __restrict__ Wl,
    float* __restrict__ C, __half* __restrict__ Ch, __half* __restrict__ Cl,
    const float* __restrict__ bias, int M, int N, int K, int lda)
{
    extern __shared__ char smc[];
    float* smf = (float*)smc;
    int tid = threadIdx.x, wid = tid >> 5;
    int m0 = blockIdx.y * 128, n0 = blockIdx.x * 128;
    int wm = (wid & 1) * 64, wn = (wid >> 1) * 32;
    uint32_t sbase = smem_u32(smc);

    wmma::fragment<wmma::accumulator,16,16,16,float> acc[4][2];
    #pragma unroll
    for (int i = 0; i < 4; i++)
        #pragma unroll
        for (int j = 0; j < 2; j++) wmma::fill_fragment(acc[i][j], 0.f);

    const int NKB = (K + 31) / 32;

    auto prefetch = [&](int kb) {
        int k0 = kb * 32, s = kb & 1;
        int soff = s * (4 * TILE_B);
        #pragma unroll
        for (int i = 0; i < 8; i++) {
            int e = tid + (i << 8);
            int arr = e >> 9, r = (e >> 2) & 127, q = e & 3;
            int off = soff + arr * TILE_B + r * 80 + q * 16;
            bool ok = (!KPAD || (k0 + q * 8 < K));
            const __half* src;
            if (arr < 2) {
                src = (arr == 0 ? Ah : Al) + (long)(m0 + r) * lda + k0 + q * 8;
            } else {
                src = (arr == 2 ? Wh : Wl) + (long)(n0 + r) * K + k0 + q * 8;
                ok = ok && (n0 + r < N);
            }
            if (ok) cpa16(sbase + off, src);
            else    *(float4*)(smc + off) = make_float4(0.f, 0.f, 0.f, 0.f);
        }
        CP_COMMIT();
    };

    prefetch(0);
    for (int kb = 0; kb < NKB; kb++) {
        int s = kb & 1;
        if (kb + 1 < NKB) { prefetch(kb + 1); CP_WAIT(1); }
        else              { CP_WAIT(0); }
        __syncthreads();
        const char* st = smc + s * (4 * TILE_B);
        const __half* pAh = (const __half*)(st);
        const __half* pAl = (const __half*)(st + TILE_B);
        const __half* pBh = (const __half*)(st + 2*TILE_B);
        const __half* pBl = (const __half*)(st + 3*TILE_B);
        #pragma unroll
        for (int ks = 0; ks < 2; ks++) {
            HB bh[2], bl[2];
            #pragma unroll
            for (int j = 0; j < 2; j++) {
                wmma::load_matrix_sync(bh[j], pBh + (wn + j*16) * HST + ks*16, HST);
                wmma::load_matrix_sync(bl[j], pBl + (wn + j*16) * HST + ks*16, HST);
            }
            #pragma unroll
            for (int i = 0; i < 4; i++) {
                HA ah, al;
                wmma::load_matrix_sync(ah, pAh + (wm + i*16) * HST + ks*16, HST);
                wmma::load_matrix_sync(al, pAl + (wm + i*16) * HST + ks*16, HST);
                #pragma unroll
                for (int j = 0; j < 2; j++) {
                    wmma::mma_sync(acc[i][j], ah, bh[j], acc[i][j]);
                    wmma::mma_sync(acc[i][j], ah, bl[j], acc[i][j]);
                    wmma::mma_sync(acc[i][j], al, bh[j], acc[i][j]);
                }
            }
        }
        __syncthreads();
    }

    /* stage C through shared for coalesced, epilogued global stores */
    #pragma unroll
    for (int i = 0; i < 4; i++)
        #pragma unroll
        for (int j = 0; j < 2; j++)
            wmma::store_matrix_sync(smf + (wm + i*16) * STG + wn + j*16,
                                    acc[i][j], STG, wmma::mem_row_major);
    __syncthreads();
    #pragma unroll
    for (int it = 0; it < 16; it++) {
        int e = tid + (it << 8);
        int r = e >> 5, c4 = (e & 31) << 2;
        int n = n0 + c4;
        if (n < N) {
            float4 v = *(float4*)(smf + r * STG + c4);
            if (EPI == 1) {
                v.x = v.x > 0.f ? v.x : 0.01f * v.x;
                v.y = v.y > 0.f ? v.y : 0.01f * v.y;
                v.z = v.z > 0.f ? v.z : 0.01f * v.z;
                v.w = v.w > 0.f ? v.w : 0.01f * v.w;
            } else if (EPI == 2) {
                v.x += bias[n];     v.y += bias[n + 1];
                v.z += bias[n + 2]; v.w += bias[n + 3];
                v.x = (v.x > 20.f) ? v.x : log1pf(__expf(v.x));
                v.y = (v.y > 20.f) ? v.y : log1pf(__expf(v.y));
                v.z = (v.z > 20.f) ? v.z : log1pf(__expf(v.z));
                v.w = (v.w > 20.f) ? v.w : log1pf(__expf(v.w));
            }
            long off = (long)(m0 + r) * N + n;
            *(float4*)(C + off) = v;
            if (SPLITC) {
                __half hx = __float2half_rn(v.x), hy = __float2half_rn(v.y);
                __half hz = __float2half_rn(v.z), hw = __float2half_rn(v.w);
                *(__half2*)(Ch + off)     = __halves2half2(hx, hy);
                *(__half2*)(Ch + off + 2) = __halves2half2(hz, hw);
                *(__half2*)(Cl + off)     = __halves2half2(
                    __float2half_rn(v.x - __half2float(hx)),
                    __float2half_rn(v.y - __half2float(hy)));
                *(__half2*)(Cl + off + 2) = __halves2half2(
                    __float2half_rn(v.z - __half2float(hz)),
                    __float2half_rn(v.w - __half2float(hw)));
            }
        }
    }
}

/* ---------------- 1. BatchNorm3d(eval) + LeakyReLU ---------------------- */
__global__ void bn_lrelu_k(const float* __restrict__ x, const float* __restrict__ g,
                           const float* __restrict__ be, const float* __restrict__ mu,
                           const float* __restrict__ var) {
    int i = blockIdx.x * 256 + threadIdx.x;
    if (i >= 2*DM*SEQL) return;
    int c = (i / SEQL) % DM;
    float v = (x[i] - mu[c]) * rsqrtf(var[c] + 1e-5f) * g[c] + be[c];
    g_act1[i] = v > 0.f ? v : 0.01f * v;
}

/* ---------------- 2. depthwise conv3d 3x3x3 SAME ------------------------ */
__global__ void dwconv_k(const float* __restrict__ wt) {
    int i = blockIdx.x * 256 + threadIdx.x;
    if (i >= 2*DM*SEQL) return;
    int w = i & 15, h = (i >> 4) & 15, d = (i >> 8) & 7;
    int c = (i >> 11) % DM;
    int b = i / (DM * SEQL);
    const float* wp = wt + c * 27;
    const float* ip = g_act1 + (size_t)(b*DM + c) * SEQL;
    float acc = 0.f;
    #pragma unroll
    for (int kd = 0; kd < 3; kd++) {
        int dd = d + kd - 1; if (dd < 0 || dd > 7) continue;
        #pragma unroll
        for (int kh = 0; kh < 3; kh++) {
            int hh = h + kh - 1; if (hh < 0 || hh > 15) continue;
            #pragma unroll
            for (int kw = 0; kw < 3; kw++) {
                int ww = w + kw - 1; if (ww < 0 || ww > 15) continue;
                acc += wp[kd*9 + kh*3 + kw] * ip[dd*256 + hh*16 + ww];
            }
        }
    }
    g_hdw[i] = acc;
}

/* ---------------- 32x32 transpose, fp32 in -> fp16 hi/lo out ------------ */
/* in[(b*R + r)*Cc + c]  ->  hi/lo[(b*Cc + c)*R + r]                        */
__global__ void transpose_h(const float* __restrict__ in, __half* __restrict__ hi,
                            __half* __restrict__ lo, int R, int Cc) {
    __shared__ float s[32][33];
    int b = blockIdx.z, r0 = blockIdx.y * 32, c0 = blockIdx.x * 32;
    int tx = threadIdx.x, ty = threadIdx.y;     /* 32 x 8 */
    #pragma unroll
    for (int i = 0; i < 4; i++)
        s[ty + i*8][tx] = in[((long)(b * R + r0 + ty + i*8)) * Cc + c0 + tx];
    __syncthreads();
    #pragma unroll
    for (int i = 0; i < 4; i++) {
        float v = s[tx][ty + i*8];
        __half hv = __float2half_rn(v);
        long o = ((long)(b * Cc + c0 + ty + i*8)) * R + r0 + tx;
        hi[o] = hv;
        lo[o] = __float2half_rn(v - __half2float(hv));
    }
}

/* ---------------- fp32 transpose (for dt) ------------------------------- */
__global__ void transpose_g(const float* __restrict__ in, float* __restrict__ out,
                            int R, int Cc) {
    __shared__ float s[32][33];
    int b = blockIdx.z, r0 = blockIdx.y * 32, c0 = blockIdx.x * 32;
    int tx = threadIdx.x, ty = threadIdx.y;     /* 32 x 8 */
    #pragma unroll
    for (int i = 0; i < 4; i++)
        s[ty + i*8][tx] = in[((long)(b * R + r0 + ty + i*8)) * Cc + c0 + tx];
    __syncthreads();
    #pragma unroll
    for (int i = 0; i < 4; i++)
        out[((long)(b * Cc + c0 + ty + i*8)) * R + r0 + tx] = s[tx][ty + i*8];
}

/* ---------------- 4. LayerNorm; emit X2 halves (orig + c-flip) ---------- */
__global__ void ln_k(const float* __restrict__ gam, const float* __restrict__ bet) {
    int m = blockIdx.x;                 /* token 0..4095 */
    __shared__ float red[16];
    const float* row = g_h2 + (size_t)m * DM;
    float s = 0.f, s2 = 0.f;
    for (int c = threadIdx.x; c < DM; c += 256) { float v = row[c]; s += v; s2 += v*v; }
    #pragma unroll
    for (int o = 16; o; o >>= 1) {
        s  += __shfl_xor_sync(~0u, s, o);
        s2 += __shfl_xor_sync(~0u, s2, o);
    }
    int wid = threadIdx.x >> 5, ln = threadIdx.x & 31;
    if (ln == 0) { red[wid] = s; red[8 + wid] = s2; }
    __syncthreads();
    float ts = 0.f, ts2 = 0.f;
    #pragma unroll
    for (int i = 0; i < 8; i++) { ts += red[i]; ts2 += red[8 + i]; }
    float mu = ts / 768.f;
    float var = ts2 / 768.f - mu * mu;
    float rs = rsqrtf(var + 1e-5f);
    for (int c = threadIdx.x; c < DM; c += 256) {
        float v = (row[c] - mu) * rs * gam[c] + bet[c];
        __half hv = __float2half_rn(v);
        __half lv = __float2half_rn(v - __half2float(hv));
        size_t o0 = (size_t)m * DM + c;
        size_t o1 = (size_t)(4096 + m) * DM + (DM - 1 - c);
        g_Ah[o0] = hv; g_Al[o0] = lv;
        g_Ah[o1] = hv; g_Al[o1] = lv;
    }
}

/* ---------------- 6. causal + anti-causal depthwise conv1d + SiLU ------- */
__global__ __launch_bounds__(256) void conv1d_k(const float* __restrict__ cw,
                                                const float* __restrict__ cb) {
    __shared__ float s[32][71];
    __shared__ float sw[32][4];
    __shared__ float sb[32];
    int b = blockIdx.z, d0 = blockIdx.y * 32, t0 = blockIdx.x * 64;
    int tid = threadIdx.x;
    if (tid < 128) sw[tid >> 2][tid & 3] = cw[(d0 + (tid >> 2)) * 4 + (tid & 3)];
    if (tid < 32)  sb[tid] = cb[d0 + tid];
    for (int e = tid; e < 32 * 70; e += 256) {
        int dd = e & 31, tt = e >> 5;
        int t = t0 - 3 + tt;
        float v = 0.f;
        if (t >= 0 && t < SEQL) v = g_xz[((size_t)(b * SEQL + t)) * (2*DI) + d0 + dd];
        s[dd][tt] = v;
    }
    __syncthreads();
    int tt = tid & 63, dg = tid >> 6;
    for (int dl = dg; dl < 32; dl += 4) {
        float w0 = sw[dl][0], w1 = sw[dl][1], w2 = sw[dl][2], w3 = sw[dl][3], bb = sb[dl];
        float f = w0*s[dl][tt]   + w1*s[dl][tt+1] + w2*s[dl][tt+2] + w3*s[dl][tt+3] + bb;
        float g = w0*s[dl][tt+6] + w1*s[dl][tt+5] + w2*s[dl][tt+4] + w3*s[dl][tt+3] + bb;
        size_t o = ((size_t)(b * DI + d0 + dl)) * SEQL + t0 + tt;
        g_xmf[o] = f / (1.f + __expf(-f));
        g_xmb[o] = g / (1.f + __expf(-g));
    }
}

/* ---------------- 10. selective scan (fwd + bwd) ------------------------ */
/* per-lane partials -> XOR-swizzled shared reduction (no per-step shfl tree) */
__global__ __launch_bounds__(256) void scan_k(const float* __restrict__ A_log) {
    __shared__ float4 shbc[32][32];
    __shared__ float shred[8][32][32];
    int dir = blockIdx.z, b = blockIdx.y;
    int wid = threadIdx.x >> 5, lane = threadIdx.x & 31;
    int d = blockIdx.x * 8 + wid;
    const float* dt = (dir ? g_dtb : g_dtf) + ((size_t)(b*DI + d)) * SEQL;
    const float* xm = (dir ? g_xmb : g_xmf) + ((size_t)(b*DI + d)) * SEQL;
    const float* xp = (dir ? g_xpb : g_xpf) + (size_t)b * SEQL * XPW;
    float* y = (dir ? g_yb : g_yf) + ((size_t)(b*DI + d)) * SEQL;
    const float L2E = 1.4426950408889634f;
    float A1 = -__expf(A_log[d*DS + lane])       * L2E;
    float A2 = -__expf(A_log[d*DS + 32 + lane])  * L2E;
    float h1 = 0.f, h2 = 0.f;
    for (int s0 = 0; s0 < SEQL; s0 += 32) {
        __syncthreads();
        for (int e = threadIdx.x; e < 1024; e += 256) {
            int r = e >> 5, n = e & 31;
            int t = dir ? (SEQL - 1 - (s0 + r)) : (s0 + r);
            const float* p = xp + (size_t)t * XPW;
            shbc[r][n] = make_float4(p[48 + n], p[80 + n], p[112 + n], p[144 + n]);
        }
        int tl = dir ? (SEQL - 1 - (s0 + lane)) : (s0 + lane);
        float dtv_b = dt[tl];
        float xv_b  = xm[tl];
        __syncthreads();
        #pragma unroll
        for (int j = 0; j < 32; j++) {
            float dtv = __shfl_sync(~0u, dtv_b, j);
            float xv  = __shfl_sync(~0u, xv_b, j);
            float4 bc = shbc[j][lane];
            float e1, e2;
            asm("ex2.approx.f32 %0, %1;" : "=f"(e1) : "f"(dtv * A1));
            asm("ex2.approx.f32 %0, %1;" : "=f"(e2) : "f"(dtv * A2));
            float uu = dtv * xv;
            h1 = e1 * h1 + uu * bc.x;
            h2 = e2 * h2 + uu * bc.y;
            shred[wid][j][lane ^ j] = h1 * bc.z + h2 * bc.w;
        }
        __syncwarp();
        float sum = 0.f;
        #pragma unroll
        for (int i = 0; i < 32; i++) sum += shred[wid][lane][i ^ lane];
        y[dir ? (SEQL - 1 - s0 - lane) : (s0 + lane)] = sum;
    }
}

/* ---------------- 11. combine + gate -> u halves (token-major) ---------- */
__global__ void combine_k(const float* __restrict__ Dskip) {
    __shared__ float s[32][33];
    int b = blockIdx.z, d0 = blockIdx.y * 32, t0 = blockIdx.x * 32;
    int tx = threadIdx.x, ty = threadIdx.y;     /* 32 x 8 */
    #pragma unroll
    for (int i = 0; i < 4; i++) {
        int d = d0 + ty + i*8;
        size_t I = ((size_t)(b * DI + d)) * SEQL + t0 + tx;
        float v = g_yf[I] + g_yb[I] + Dskip[d] * (g_xmf[I] + g_xmb[I]);
        s[ty + i*8][tx] = v;
    }
    __syncthreads();
    #pragma unroll
    for (int i = 0; i < 4; i++) {
        int t = t0 + ty + i*8;
        int d = d0 + tx;
        float z = g_xz[((size_t)(b * SEQL + t)) * (2*DI) + DI + d];
        float sz = z / (1.f + __expf(-z));
        float u = s[tx][ty + i*8] * sz;
        __half hu = __float2half_rn(u);
        size_t o = ((size_t)(b * SEQL + t)) * DI + d;
        g_Ah[o] = hu;
        g_Al[o] = __float2half_rn(u - __half2float(hu));
    }
}

/* ---------------- 13. final: average 4 directions ----------------------- */
__global__ void final_k(float* __restrict__ out) {
    int i = blockIdx.x * 256 + threadIdx.x;
    if (i >= 2 * SEQL * DM) return;
    int c = i % DM;
    size_t ml = (size_t)(i / DM);
    out[i] = 0.25f * (g_v[ml * DM + c] +
                      g_v[(ml + (size_t)2 * SEQL) * DM + (DM - 1 - c)]);
}

/* ------------------------------------------------------------------------ */
static inline void split_w(const float* p, __half* h, __half* l, long n) {
    int n2 = (int)(n / 2);
    split_k<<<(n2 + 255) / 256, 256>>>(p, h, l, n2);
}

extern "C" void kernel_launch(void* const* d_in, const int* in_sizes, int n_in,
                              void* d_out, int out_size) {
    const float* x        = (const float*)d_in[0];
    const float* bn_gamma = (const float*)d_in[1];
    const float* bn_beta  = (const float*)d_in[2];
    const float* bn_mean  = (const float*)d_in[3];
    const float* bn_var   = (const float*)d_in[4];
    const float* dw_w     = (const float*)d_in[5];
    const float* pw_w     = (const float*)d_in[6];
    const float* ln_gamma = (const float*)d_in[7];
    const float* ln_beta  = (const float*)d_in[8];
    const float* W_in     = (const float*)d_in[9];
    const float* conv_w   = (const float*)d_in[10];
    const float* conv_b   = (const float*)d_in[11];
    const float* W_x      = (const float*)d_in[12];
    const float* W_dt     = (const float*)d_in[13];
    const float* b_dt     = (const float*)d_in[14];
    const float* A_log    = (const float*)d_in[15];
    const float* D_skip   = (const float*)d_in[16];
    const float* W_out    = (const float*)d_in[17];
    float* out            = (float*)d_out;

    float *p_act1, *p_hdw, *p_h2, *p_xz, *p_xmf, *p_xmb, *p_xpf, *p_xpb,
          *p_dttmf, *p_dttmb, *p_dtf, *p_dtb, *p_v;
    __half *p_Ah, *p_Al, *p_Wh, *p_Wl, *p_xph, *p_xpl;
    cudaGetSymbolAddress((void**)&p_act1, g_act1);
    cudaGetSymbolAddress((void**)&p_hdw,  g_hdw);
    cudaGetSymbolAddress((void**)&p_h2,   g_h2);
    cudaGetSymbolAddress((void**)&p_xz,   g_xz);
    cudaGetSymbolAddress((void**)&p_xmf,  g_xmf);
    cudaGetSymbolAddress((void**)&p_xmb,  g_xmb);
    cudaGetSymbolAddress((void**)&p_xpf,  g_xpf);
    cudaGetSymbolAddress((void**)&p_xpb,  g_xpb);
    cudaGetSymbolAddress((void**)&p_dttmf, g_dttmf);
    cudaGetSymbolAddress((void**)&p_dttmb, g_dttmb);
    cudaGetSymbolAddress((void**)&p_dtf,  g_dtf);
    cudaGetSymbolAddress((void**)&p_dtb,  g_dtb);
    cudaGetSymbolAddress((void**)&p_v,    g_v);
    cudaGetSymbolAddress((void**)&p_Ah,   g_Ah);
    cudaGetSymbolAddress((void**)&p_Al,   g_Al);
    cudaGetSymbolAddress((void**)&p_Wh,   g_Wh);
    cudaGetSymbolAddress((void**)&p_Wl,   g_Wl);
    cudaGetSymbolAddress((void**)&p_xph,  g_xph);
    cudaGetSymbolAddress((void**)&p_xpl,  g_xpl);

    cudaFuncSetAttribute(hmma_gemm_k<0,false,false>, cudaFuncAttributeMaxDynamicSharedMemorySize, SM_TOTAL);
    cudaFuncSetAttribute(hmma_gemm_k<0,false,true>,  cudaFuncAttributeMaxDynamicSharedMemorySize, SM_TOTAL);
    cudaFuncSetAttribute(hmma_gemm_k<1,false,false>, cudaFuncAttributeMaxDynamicSharedMemorySize, SM_TOTAL);
    cudaFuncSetAttribute(hmma_gemm_k<2,true,false>,  cudaFuncAttributeMaxDynamicSharedMemorySize, SM_TOTAL);

    /* [0..1] big weight splits first (keeps pw gemm at launch index 5 for ncu) */
    split_w(pw_w, p_Wh + OFF_PW, p_Wl + OFF_PW, (long)DM*DM);
    split_w(W_in, p_Wh + OFF_IN, p_Wl + OFF_IN, (long)2*DI*DM);
    /* [2..4] front-end */
    bn_lrelu_k<<<12288, 256>>>(x, bn_gamma, bn_beta, bn_mean, bn_var);
    dwconv_k<<<12288, 256>>>(dw_w);
    transpose_h<<<dim3(64, 24, 2), dim3(32, 8)>>>(p_hdw, p_Ah, p_Al, DM, SEQL);
    /* [5] pointwise conv: [4096,768] x [768,768]^T, leaky-relu */
    hmma_gemm_k<1,false,false><<<dim3(6, 32), 256, SM_TOTAL>>>(
        p_Ah, p_Al, p_Wh + OFF_PW, p_Wl + OFF_PW, p_h2, nullptr, nullptr,
        nullptr, 4096, DM, DM, DM);
    /* [6] layernorm -> X2 halves (orig + flip) */
    ln_k<<<2*SEQL, 256>>>(ln_gamma, ln_beta);
    /* [7] in_proj: [8192,768] x [3072,768]^T */
    hmma_gemm_k<0,false,false><<<dim3(24, 64), 256, SM_TOTAL>>>(
        p_Ah, p_Al, p_Wh + OFF_IN, p_Wl + OFF_IN, p_xz, nullptr, nullptr,
        nullptr, MTOK, 2*DI, DM, DM);
    /* remaining weight splits */
    split_w(W_x,   p_Wh + OFF_X,   p_Wl + OFF_X,   (long)XPW*DI);
    split_w(W_dt,  p_Wh + OFF_DT,  p_Wl + OFF_DT,  (long)DI*DTR);
    split_w(W_out, p_Wh + OFF_OUT, p_Wl + OFF_OUT, (long)DM*DI);
    /* dual-direction conv1d + SiLU -> xm [b,d,t] */
    conv1d_k<<<dim3(32, 48, NB), 256>>>(conv_w, conv_b);
    /* x_proj (f): xm -> token-major halves -> gemm (emits xp fp32 + halves) */
    transpose_h<<<dim3(64, 48, NB), dim3(32, 8)>>>(p_xmf, p_Ah, p_Al, DI, SEQL);
    hmma_gemm_k<0,false,true><<<dim3(2, 64), 256, SM_TOTAL>>>(
        p_Ah, p_Al, p_Wh + OFF_X, p_Wl + OFF_X, p_xpf, p_xph, p_xpl,
        nullptr, MTOK, XPW, DI, DI);
    /* x_proj (b) */
    transpose_h<<<dim3(64, 48, NB), dim3(32, 8)>>>(p_xmb, p_Ah, p_Al, DI, SEQL);
    hmma_gemm_k<0,false,true><<<dim3(2, 64), 256, SM_TOTAL>>>(
        p_Ah, p_Al, p_Wh + OFF_X, p_Wl + OFF_X, p_xpb,
        p_xph + (long)MTOK*XPW, p_xpl + (long)MTOK*XPW,
        nullptr, MTOK, XPW, DI, DI);
    /* dt proj + softplus: A = xp halves [8192, K=48 (lda=176)] */
    hmma_gemm_k<2,true,false><<<dim3(12, 64), 256, SM_TOTAL>>>(
        p_xph, p_xpl, p_Wh + OFF_DT, p_Wl + OFF_DT, p_dttmf, nullptr, nullptr,
        b_dt, MTOK, DI, DTR, XPW);
    hmma_gemm_k<2,true,false><<<dim3(12, 64), 256, SM_TOTAL>>>(
        p_xph + (long)MTOK*XPW, p_xpl + (long)MTOK*XPW,
        p_Wh + OFF_DT, p_Wl + OFF_DT, p_dttmb, nullptr, nullptr,
        b_dt, MTOK, DI, DTR, XPW);
    /* dt token-major -> [b,d,t] */
    transpose_g<<<dim3(48, 64, NB), dim3(32, 8)>>>(p_dttmf, p_dtf, SEQL, DI);
    transpose_g<<<dim3(48, 64, NB), dim3(32, 8)>>>(p_dttmb, p_dtb, SEQL, DI);
    /* selective scan */
    scan_k<<<dim3(DI/8, NB, 2), 256>>>(A_log);
    /* combine + gate -> u halves */
    combine_k<<<dim3(64, 48, NB), dim3(32, 8)>>>(D_skip);
    /* out_proj: [8192,1536] x [768,1536]^T */
    hmma_gemm_k<0,false,false><<<dim3(6, 64), 256, SM_TOTAL>>>(
        p_Ah, p_Al, p_Wh + OFF_OUT, p_Wl + OFF_OUT, p_v, nullptr, nullptr,
        nullptr, MTOK, DM, DI, DI);
    final_k<<<12288, 256>>>(out);
    (void)in_sizes; (void)n_in; (void)out_size;
}